// round 2
// baseline (speedup 1.0000x reference)
#include <cuda_runtime.h>
#include <math.h>

#define NT    4096
#define D     512
#define NHD   16
#define DH    32
#define DEPTH 3
#define DMLP  2048
#define GENES 250
#define GH    64
#define GW    64

// ---------------- scratch (device globals; no allocation allowed) -----------
__device__ float g_x[NT * D];
__device__ float g_xn[NT * D];
__device__ float g_qkv[NT * 3 * D];
__device__ float g_ao[NT * D];
__device__ float g_h[NT * DMLP];
__device__ float g_grid[GH * GW * D];   // [cell][d], D-coalesced
__device__ float g_conv[GH * GW * D];

// ---------------- LayerNorm: one block per row, 128 threads -----------------
__global__ void ln_kernel(const float* __restrict__ in, float* __restrict__ out,
                          const float* __restrict__ gam, const float* __restrict__ bet) {
    int row = blockIdx.x;
    int t   = threadIdx.x;            // 128 threads * float4 = 512
    const float4* xp = (const float4*)(in + (size_t)row * D);
    float4 v = xp[t];
    float s  = v.x + v.y + v.z + v.w;
    float ss = v.x * v.x + v.y * v.y + v.z * v.z + v.w * v.w;
#pragma unroll
    for (int off = 16; off; off >>= 1) {
        s  += __shfl_xor_sync(0xffffffffu, s, off);
        ss += __shfl_xor_sync(0xffffffffu, ss, off);
    }
    __shared__ float sb[4], ssb[4];
    int w = t >> 5, lane = t & 31;
    if (lane == 0) { sb[w] = s; ssb[w] = ss; }
    __syncthreads();
    s  = sb[0] + sb[1] + sb[2] + sb[3];
    ss = ssb[0] + ssb[1] + ssb[2] + ssb[3];
    float mean = s * (1.0f / D);
    float var  = ss * (1.0f / D) - mean * mean;
    float inv  = rsqrtf(var + 1e-5f);
    float4 g4 = ((const float4*)gam)[t];
    float4 b4 = ((const float4*)bet)[t];
    float4 o;
    o.x = (v.x - mean) * inv * g4.x + b4.x;
    o.y = (v.y - mean) * inv * g4.y + b4.y;
    o.z = (v.z - mean) * inv * g4.z + b4.z;
    o.w = (v.w - mean) * inv * g4.w + b4.w;
    ((float4*)(out + (size_t)row * D))[t] = o;
}

// ---------------- GEMM: C[M,OUT] = A[M,K] @ W[OUT,K]^T (+bias, epilogue) ----
// MODE 0: C = v + bias
// MODE 1: C = gelu_exact(v + bias)
// MODE 2: C = res + v + bias
template <int MODE>
__global__ void __launch_bounds__(256) gemm_kernel(
    const float* __restrict__ A, const float* __restrict__ W,
    const float* __restrict__ bias, const float* __restrict__ res,
    float* __restrict__ C, int M, int OUT, int K) {
    __shared__ __align__(16) float As[16][64];
    __shared__ __align__(16) float Bs[16][64];
    int t  = threadIdx.x;
    int tx = t & 15, ty = t >> 4;
    int bx = blockIdx.x, by = blockIdx.y;
    int r  = t >> 2, c4 = t & 3;     // loader mapping: 64 rows x 4 float4
    int arow = by * 64 + r;
    int brow = bx * 64 + r;
    float acc[4][4];
#pragma unroll
    for (int i = 0; i < 4; i++)
#pragma unroll
        for (int j = 0; j < 4; j++) acc[i][j] = 0.f;

    for (int kt = 0; kt < K; kt += 16) {
        float4 a = *(const float4*)(A + (size_t)arow * K + kt + c4 * 4);
        float4 bv = make_float4(0.f, 0.f, 0.f, 0.f);
        if (brow < OUT) bv = *(const float4*)(W + (size_t)brow * K + kt + c4 * 4);
        __syncthreads();
        As[c4 * 4 + 0][r] = a.x;  As[c4 * 4 + 1][r] = a.y;
        As[c4 * 4 + 2][r] = a.z;  As[c4 * 4 + 3][r] = a.w;
        Bs[c4 * 4 + 0][r] = bv.x; Bs[c4 * 4 + 1][r] = bv.y;
        Bs[c4 * 4 + 2][r] = bv.z; Bs[c4 * 4 + 3][r] = bv.w;
        __syncthreads();
#pragma unroll
        for (int k = 0; k < 16; k++) {
            float4 av = *(const float4*)&As[k][ty * 4];
            float4 bw = *(const float4*)&Bs[k][tx * 4];
            acc[0][0] += av.x * bw.x; acc[0][1] += av.x * bw.y; acc[0][2] += av.x * bw.z; acc[0][3] += av.x * bw.w;
            acc[1][0] += av.y * bw.x; acc[1][1] += av.y * bw.y; acc[1][2] += av.y * bw.z; acc[1][3] += av.y * bw.w;
            acc[2][0] += av.z * bw.x; acc[2][1] += av.z * bw.y; acc[2][2] += av.z * bw.z; acc[2][3] += av.z * bw.w;
            acc[3][0] += av.w * bw.x; acc[3][1] += av.w * bw.y; acc[3][2] += av.w * bw.z; acc[3][3] += av.w * bw.w;
        }
    }
#pragma unroll
    for (int i = 0; i < 4; i++) {
        int row = by * 64 + ty * 4 + i;
#pragma unroll
        for (int j = 0; j < 4; j++) {
            int col = bx * 64 + tx * 4 + j;
            if (col < OUT) {
                float v = acc[i][j] + bias[col];
                if (MODE == 1) v = 0.5f * v * (1.0f + erff(v * 0.70710678118654752f));
                if (MODE == 2) v += res[(size_t)row * OUT + col];
                C[(size_t)row * OUT + col] = v;
            }
        }
    }
}

// ---------------- Flash attention: thread = one (head, query) row ----------
__global__ void __launch_bounds__(128) attn_kernel() {
    int h   = blockIdx.x;
    int row = blockIdx.y * 128 + threadIdx.x;
    __shared__ float4 Ks[128][8];
    __shared__ float4 Vs[128][8];
    float4 q[8];
    const float4* qp = (const float4*)(g_qkv + (size_t)row * (3 * D) + h * DH);
#pragma unroll
    for (int dd = 0; dd < 8; dd++) q[dd] = qp[dd];
    float m = -1e30f, l = 0.f;
    float o[32];
#pragma unroll
    for (int d = 0; d < 32; d++) o[d] = 0.f;
    const float scale = 0.17677669529663687f;   // 1/sqrt(32)

    for (int j0 = 0; j0 < NT; j0 += 128) {
#pragma unroll
        for (int i = 0; i < 8; i++) {
            int lin = i * 128 + threadIdx.x;
            int j = lin >> 3, dd = lin & 7;
            const float* base = g_qkv + (size_t)(j0 + j) * (3 * D) + h * DH;
            Ks[j][dd] = ((const float4*)(base + D))[dd];
            Vs[j][dd] = ((const float4*)(base + 2 * D))[dd];
        }
        __syncthreads();
        for (int j = 0; j < 128; j++) {
            float s = 0.f;
#pragma unroll
            for (int dd = 0; dd < 8; dd++) {
                float4 k4 = Ks[j][dd];
                s += q[dd].x * k4.x; s += q[dd].y * k4.y;
                s += q[dd].z * k4.z; s += q[dd].w * k4.w;
            }
            s *= scale;
            if (s > m) {                 // rare: rescale accumulators
                float corr = __expf(m - s);
                l *= corr;
#pragma unroll
                for (int d = 0; d < 32; d++) o[d] *= corr;
                m = s;
            }
            float p = __expf(s - m);
            l += p;
#pragma unroll
            for (int dd = 0; dd < 8; dd++) {
                float4 v4 = Vs[j][dd];
                o[dd * 4 + 0] += p * v4.x; o[dd * 4 + 1] += p * v4.y;
                o[dd * 4 + 2] += p * v4.z; o[dd * 4 + 3] += p * v4.w;
            }
        }
        __syncthreads();
    }
    float inv = 1.f / l;
    float* op = g_ao + (size_t)row * D + h * DH;
#pragma unroll
    for (int d = 0; d < 32; d++) op[d] = o[d] * inv;
}

// ---------------- depthwise conv on 64x64 grid ------------------------------
__global__ void scatter_kernel(const int* __restrict__ coords) {
    int idx = blockIdx.x * blockDim.x + threadIdx.x;   // NT * (D/4)
    int n  = idx >> 7;          // D/4 = 128
    int d4 = idx & 127;
    int rr = coords[2 * n], cc = coords[2 * n + 1];
    ((float4*)g_grid)[(size_t)(rr * GW + cc) * 128 + d4] =
        ((const float4*)g_x)[(size_t)n * 128 + d4];
}

__global__ void conv_kernel(const float* __restrict__ ck) {
    int idx = blockIdx.x * blockDim.x + threadIdx.x;   // GH*GW*D
    int d    = idx & (D - 1);
    int cell = idx >> 9;
    int r = cell >> 6, c = cell & 63;
    float acc = 0.f;
#pragma unroll
    for (int kh = 0; kh < 3; kh++) {
        int rr = r + kh - 1;
        if (rr < 0 || rr >= GH) continue;
#pragma unroll
        for (int kw = 0; kw < 3; kw++) {
            int cc = c + kw - 1;
            if (cc < 0 || cc >= GW) continue;
            acc += ck[d * 9 + kh * 3 + kw] * g_grid[(size_t)(rr * GW + cc) * D + d];
        }
    }
    g_conv[(size_t)cell * D + d] = acc;
}

__global__ void gather_kernel(const int* __restrict__ coords, const float* __restrict__ cb) {
    int idx = blockIdx.x * blockDim.x + threadIdx.x;   // NT*D
    int n = idx >> 9, d = idx & (D - 1);
    int rr = coords[2 * n], cc = coords[2 * n + 1];
    g_x[idx] += g_conv[(size_t)(rr * GW + cc) * D + d] + cb[d];
}

// ---------------- host launch ------------------------------------------------
extern "C" void kernel_launch(void* const* d_in, const int* in_sizes, int n_in,
                              void* d_out, int out_size) {
    const float* gf     = (const float*)d_in[0];
    const int*   coords = (const int*)d_in[1];
    int wi = (n_in >= 22) ? 4 : 2;   // skip grid_h/grid_w scalars if present
    const float* ln1_g = (const float*)d_in[wi + 0];
    const float* ln1_b = (const float*)d_in[wi + 1];
    const float* wqkv  = (const float*)d_in[wi + 2];
    const float* bqkv  = (const float*)d_in[wi + 3];
    const float* wo    = (const float*)d_in[wi + 4];
    const float* bo    = (const float*)d_in[wi + 5];
    const float* ln2_g = (const float*)d_in[wi + 6];
    const float* ln2_b = (const float*)d_in[wi + 7];
    const float* w1    = (const float*)d_in[wi + 8];
    const float* b1    = (const float*)d_in[wi + 9];
    const float* w2    = (const float*)d_in[wi + 10];
    const float* b2    = (const float*)d_in[wi + 11];
    const float* ck    = (const float*)d_in[wi + 12];
    const float* cb    = (const float*)d_in[wi + 13];
    const float* lnf_g = (const float*)d_in[wi + 14];
    const float* lnf_b = (const float*)d_in[wi + 15];
    const float* wp    = (const float*)d_in[wi + 16];
    const float* bp    = (const float*)d_in[wi + 17];

    float* out_x    = (float*)d_out;
    float* out_pred = out_x + (size_t)NT * D;

    static float *px = nullptr, *pxn, *pqkv, *pao, *ph;
    if (!px) {
        cudaGetSymbolAddress((void**)&px,   g_x);
        cudaGetSymbolAddress((void**)&pxn,  g_xn);
        cudaGetSymbolAddress((void**)&pqkv, g_qkv);
        cudaGetSymbolAddress((void**)&pao,  g_ao);
        cudaGetSymbolAddress((void**)&ph,   g_h);
    }

    cudaMemcpyAsync(px, gf, (size_t)NT * D * sizeof(float), cudaMemcpyDeviceToDevice);

    for (int i = 0; i < DEPTH; i++) {
        ln_kernel<<<NT, 128>>>(px, pxn, ln1_g + i * D, ln1_b + i * D);
        gemm_kernel<0><<<dim3(3 * D / 64, NT / 64), 256>>>(
            pxn, wqkv + (size_t)i * 3 * D * D, bqkv + i * 3 * D, nullptr, pqkv, NT, 3 * D, D);
        attn_kernel<<<dim3(NHD, NT / 128), 128>>>();
        gemm_kernel<2><<<dim3(D / 64, NT / 64), 256>>>(
            pao, wo + (size_t)i * D * D, bo + i * D, px, px, NT, D, D);
        ln_kernel<<<NT, 128>>>(px, pxn, ln2_g + i * D, ln2_b + i * D);
        gemm_kernel<1><<<dim3(DMLP / 64, NT / 64), 256>>>(
            pxn, w1 + (size_t)i * DMLP * D, b1 + i * DMLP, nullptr, ph, NT, DMLP, D);
        gemm_kernel<2><<<dim3(D / 64, NT / 64), 256>>>(
            ph, w2 + (size_t)i * D * DMLP, b2 + i * D, px, px, NT, D, DMLP);
        scatter_kernel<<<NT * (D / 4) / 256, 256>>>(coords);
        conv_kernel<<<GH * GW * D / 256, 256>>>(ck + (size_t)i * D * 9);
        gather_kernel<<<NT * D / 256, 256>>>(coords, cb + i * D);
    }
    ln_kernel<<<NT, 128>>>(px, out_x, lnf_g, lnf_b);
    gemm_kernel<0><<<dim3((GENES + 63) / 64, NT / 64), 256>>>(
        out_x, wp, bp, nullptr, out_pred, NT, GENES, D);
}

// round 4
// speedup vs baseline: 1.6445x; 1.6445x over previous
#include <cuda_runtime.h>
#include <cuda_bf16.h>
#include <math.h>
#include <stdint.h>

#define NT    4096
#define D     512
#define NHD   16
#define DH    32
#define DEPTH 3
#define DMLP  2048
#define GENES 250
#define GH    64
#define GW    64

// ---------------- PTX helpers ----------------
__device__ __forceinline__ uint32_t smem_u32(const void* p) {
    uint32_t a;
    asm("{ .reg .u64 t; cvta.to.shared.u64 t, %1; cvt.u32.u64 %0, t; }" : "=r"(a) : "l"(p));
    return a;
}
#define CP_ASYNC16(sa, ga) \
    asm volatile("cp.async.cg.shared.global [%0], [%1], 16;" :: "r"(sa), "l"(ga))
#define CP_COMMIT() asm volatile("cp.async.commit_group;")
#define CP_WAIT(n)  asm volatile("cp.async.wait_group %0;" :: "n"(n))

#define LDSM4(r0, r1, r2, r3, addr) \
    asm volatile("ldmatrix.sync.aligned.m8n8.x4.shared.b16 {%0,%1,%2,%3}, [%4];" \
        : "=r"(r0), "=r"(r1), "=r"(r2), "=r"(r3) : "r"(addr))

__device__ __forceinline__ void mma_bf16(float* d, const uint32_t* a, const uint32_t* b) {
    asm volatile("mma.sync.aligned.m16n8k16.row.col.f32.bf16.bf16.f32 "
        "{%0,%1,%2,%3}, {%4,%5,%6,%7}, {%8,%9}, {%0,%1,%2,%3};"
        : "+f"(d[0]), "+f"(d[1]), "+f"(d[2]), "+f"(d[3])
        : "r"(a[0]), "r"(a[1]), "r"(a[2]), "r"(a[3]), "r"(b[0]), "r"(b[1]));
}

#define FMA2(d, a, b) asm("fma.rn.f32x2 %0, %1, %2, %0;" : "+l"(d) : "l"(a), "l"(b))
#define MUL2(d, c)    asm("mul.rn.f32x2 %0, %0, %1;" : "+l"(d) : "l"(c))
#define PACK2(d, x, y) asm("mov.b64 %0, {%1, %2};" : "=l"(d) : "f"(x), "f"(y))
#define UNPACK2(x, y, d) asm("mov.b64 {%0, %1}, %2;" : "=f"(x), "=f"(y) : "l"(d))
#define LDSV2(a, b, addr) asm volatile("ld.shared.v2.b64 {%0, %1}, [%2];" : "=l"(a), "=l"(b) : "r"(addr))

__device__ __forceinline__ void hilo(float v, __nv_bfloat16& h, __nv_bfloat16& l) {
    h = __float2bfloat16(v);
    l = __float2bfloat16(v - __bfloat162float(h));
}

// ---------------- device scratch ----------------
__device__ float g_x[NT * D];
__device__ float g_qkv[NT * 3 * D];
__device__ float g_grid[GH * GW * D];
__device__ float g_conv[GH * GW * D];
__device__ __nv_bfloat16 g_xn_h[NT * D],  g_xn_l[NT * D];
__device__ __nv_bfloat16 g_ao_h[NT * D],  g_ao_l[NT * D];
__device__ __nv_bfloat16 g_hh[NT * DMLP], g_hl[NT * DMLP];
__device__ __nv_bfloat16 g_xf_h[NT * D],  g_xf_l[NT * D];
__device__ __nv_bfloat16 g_wqkv_h[DEPTH * 3 * D * D], g_wqkv_l[DEPTH * 3 * D * D];
__device__ __nv_bfloat16 g_wo_h[DEPTH * D * D],       g_wo_l[DEPTH * D * D];
__device__ __nv_bfloat16 g_w1_h[DEPTH * DMLP * D],    g_w1_l[DEPTH * DMLP * D];
__device__ __nv_bfloat16 g_w2_h[DEPTH * D * DMLP],    g_w2_l[DEPTH * D * DMLP];
__device__ __nv_bfloat16 g_wp_h[GENES * D],           g_wp_l[GENES * D];

__global__ void cvt_kernel(const float* __restrict__ s, __nv_bfloat16* __restrict__ h,
                           __nv_bfloat16* __restrict__ l, int n) {
    int i = blockIdx.x * blockDim.x + threadIdx.x;
    if (i < n) { __nv_bfloat16 a, b; hilo(s[i], a, b); h[i] = a; l[i] = b; }
}

// ---------------- LayerNorm -> bf16 hi/lo (optionally fp32 copy) -----------
template <int WF32>
__global__ void ln_kernel(const float* __restrict__ in, float* __restrict__ out32,
                          __nv_bfloat16* __restrict__ oh, __nv_bfloat16* __restrict__ ol,
                          const float* __restrict__ gam, const float* __restrict__ bet) {
    int row = blockIdx.x, t = threadIdx.x;
    float4 v = ((const float4*)(in + (size_t)row * D))[t];
    float s = v.x + v.y + v.z + v.w;
    float ss = v.x * v.x + v.y * v.y + v.z * v.z + v.w * v.w;
#pragma unroll
    for (int off = 16; off; off >>= 1) {
        s  += __shfl_xor_sync(0xffffffffu, s, off);
        ss += __shfl_xor_sync(0xffffffffu, ss, off);
    }
    __shared__ float sb[4], ssb[4];
    int w = t >> 5, lane = t & 31;
    if (lane == 0) { sb[w] = s; ssb[w] = ss; }
    __syncthreads();
    s = sb[0] + sb[1] + sb[2] + sb[3];
    ss = ssb[0] + ssb[1] + ssb[2] + ssb[3];
    float mean = s * (1.0f / D);
    float inv = rsqrtf(ss * (1.0f / D) - mean * mean + 1e-5f);
    float4 g4 = ((const float4*)gam)[t];
    float4 b4 = ((const float4*)bet)[t];
    float o0 = (v.x - mean) * inv * g4.x + b4.x;
    float o1 = (v.y - mean) * inv * g4.y + b4.y;
    float o2 = (v.z - mean) * inv * g4.z + b4.z;
    float o3 = (v.w - mean) * inv * g4.w + b4.w;
    size_t base = (size_t)row * D + t * 4;
    __nv_bfloat16 h0, l0, h1, l1, h2, l2, h3, l3;
    hilo(o0, h0, l0); hilo(o1, h1, l1); hilo(o2, h2, l2); hilo(o3, h3, l3);
    __nv_bfloat162 p;
    p.x = h0; p.y = h1; *(__nv_bfloat162*)(oh + base) = p;
    p.x = h2; p.y = h3; *(__nv_bfloat162*)(oh + base + 2) = p;
    p.x = l0; p.y = l1; *(__nv_bfloat162*)(ol + base) = p;
    p.x = l2; p.y = l3; *(__nv_bfloat162*)(ol + base + 2) = p;
    if (WF32) {
        float4 o; o.x = o0; o.y = o1; o.z = o2; o.w = o3;
        ((float4*)(out32 + (size_t)row * D))[t] = o;
    }
}

// ---------------- bf16 hi/lo 3-term GEMM via mma.sync (HMMA) ----------------
// C[M,OUT] = A[M,K] @ W[OUT,K]^T + bias (+epilogue). 128x128 tile, BK=32.
// smem tile: [128][40] bf16 (80B pitch). Stage = 4 tiles (Ah,Al,Wh,Wl).
#define TPITCH 80
#define TILE_B (128 * TPITCH)            // 10240
#define STAGE_B (4 * TILE_B)             // 40960
#define GEMM_DYN (2 * STAGE_B)           // 81920

__device__ __forceinline__ void stage_load(
    uint32_t sbase, const __nv_bfloat16* Ah, const __nv_bfloat16* Al,
    const __nv_bfloat16* Wh, const __nv_bfloat16* Wl,
    int mrow, int ncol, int OUT, int K, int kt, int tid) {
#pragma unroll
    for (int i = 0; i < 2; i++) {
        int chunk = tid + i * 256;            // 0..511
        int r = chunk >> 2, c16 = chunk & 3;  // row, 16B-chunk in row
        uint32_t so = (uint32_t)(r * TPITCH + c16 * 16);
        size_t aoff = (size_t)(mrow + r) * K + kt + c16 * 8;
        int wr = ncol + r; if (wr >= OUT) wr = OUT - 1;
        size_t woff = (size_t)wr * K + kt + c16 * 8;
        CP_ASYNC16(sbase + so,              (const char*)(Ah + aoff));
        CP_ASYNC16(sbase + TILE_B + so,     (const char*)(Al + aoff));
        CP_ASYNC16(sbase + 2 * TILE_B + so, (const char*)(Wh + woff));
        CP_ASYNC16(sbase + 3 * TILE_B + so, (const char*)(Wl + woff));
    }
}

// MODE 0: out32 = v+bias ; MODE 1: outh/outl = hilo(gelu(v+bias)) ; MODE 2: out32 += v+bias
template <int MODE>
__global__ void __launch_bounds__(256) gemm_mma(
    const __nv_bfloat16* __restrict__ Ah, const __nv_bfloat16* __restrict__ Al,
    const __nv_bfloat16* __restrict__ Wh, const __nv_bfloat16* __restrict__ Wl,
    const float* __restrict__ bias, float* __restrict__ out32,
    __nv_bfloat16* __restrict__ outh, __nv_bfloat16* __restrict__ outl,
    int OUT, int K) {
    extern __shared__ char dyn_raw[];
    const int tid = threadIdx.x, wid = tid >> 5, lane = tid & 31;
    const int mrow = blockIdx.y * 128, ncol = blockIdx.x * 128;
    const int warp_m = wid & 1, warp_n = wid >> 1;   // 2 x 4
    const int m_off = warp_m * 64, n_off = warp_n * 32;
    const int NIT = K >> 5;
    uint32_t smem0 = smem_u32(dyn_raw);

    float acc[4][4][4];
#pragma unroll
    for (int a = 0; a < 4; a++)
#pragma unroll
        for (int b = 0; b < 4; b++)
#pragma unroll
            for (int c = 0; c < 4; c++) acc[a][b][c] = 0.f;

    // per-thread ldmatrix address components
    const uint32_t a_lm = (uint32_t)((m_off + (lane & 15)) * TPITCH + (lane & 16));
    const int bl = lane & 7, bg = (lane >> 3) & 3;
    const uint32_t b_lm = (uint32_t)((n_off + ((bg >> 1) << 3) + bl) * TPITCH + ((bg & 1) << 4));

    stage_load(smem0, Ah, Al, Wh, Wl, mrow, ncol, OUT, K, 0, tid);
    CP_COMMIT();

    for (int it = 0; it < NIT; it++) {
        if (it + 1 < NIT) {
            stage_load(smem0 + ((it + 1) & 1) * STAGE_B, Ah, Al, Wh, Wl,
                       mrow, ncol, OUT, K, (it + 1) * 32, tid);
            CP_COMMIT();
            CP_WAIT(1);
        } else {
            CP_WAIT(0);
        }
        __syncthreads();
        uint32_t sb = smem0 + (it & 1) * STAGE_B;
#pragma unroll
        for (int ks = 0; ks < 2; ks++) {
            uint32_t kb = (uint32_t)(ks * 32);   // 16 bf16 = 32B
            uint32_t ah[4][4], al[4][4], bh[4][2], bl2[4][2];
#pragma unroll
            for (int mt = 0; mt < 4; mt++) {
                uint32_t ad = sb + a_lm + mt * (16 * TPITCH) + kb;
                LDSM4(ah[mt][0], ah[mt][1], ah[mt][2], ah[mt][3], ad);
                LDSM4(al[mt][0], al[mt][1], al[mt][2], al[mt][3], ad + TILE_B);
            }
#pragma unroll
            for (int np = 0; np < 2; np++) {
                uint32_t bd = sb + 2 * TILE_B + b_lm + np * (16 * TPITCH) + kb;
                LDSM4(bh[2 * np][0], bh[2 * np][1], bh[2 * np + 1][0], bh[2 * np + 1][1], bd);
                LDSM4(bl2[2 * np][0], bl2[2 * np][1], bl2[2 * np + 1][0], bl2[2 * np + 1][1], bd + TILE_B);
            }
#pragma unroll
            for (int mt = 0; mt < 4; mt++)
#pragma unroll
                for (int nt = 0; nt < 4; nt++) {
                    mma_bf16(acc[mt][nt], ah[mt], bh[nt]);
                    mma_bf16(acc[mt][nt], ah[mt], bl2[nt]);
                    mma_bf16(acc[mt][nt], al[mt], bh[nt]);
                }
        }
        __syncthreads();
    }

    // epilogue
    const int r0 = lane >> 2, cp = (lane & 3) * 2;
#pragma unroll
    for (int mt = 0; mt < 4; mt++)
#pragma unroll
        for (int nt = 0; nt < 4; nt++) {
            int col = ncol + n_off + nt * 8 + cp;
            if (col >= OUT) continue;
            float bx = bias[col], by = bias[col + 1];
#pragma unroll
            for (int half = 0; half < 2; half++) {
                int row = mrow + m_off + mt * 16 + r0 + half * 8;
                float vx = acc[mt][nt][2 * half] + bx;
                float vy = acc[mt][nt][2 * half + 1] + by;
                size_t idx = (size_t)row * OUT + col;
                if (MODE == 0) {
                    *(float2*)(out32 + idx) = make_float2(vx, vy);
                } else if (MODE == 1) {
                    float gx = 0.5f * vx * (1.0f + erff(vx * 0.70710678118654752f));
                    float gy = 0.5f * vy * (1.0f + erff(vy * 0.70710678118654752f));
                    __nv_bfloat16 hx, lx, hy, ly;
                    hilo(gx, hx, lx); hilo(gy, hy, ly);
                    __nv_bfloat162 p;
                    p.x = hx; p.y = hy; *(__nv_bfloat162*)(outh + idx) = p;
                    p.x = lx; p.y = ly; *(__nv_bfloat162*)(outl + idx) = p;
                } else {
                    float2 o = *(float2*)(out32 + idx);
                    o.x += vx; o.y += vy;
                    *(float2*)(out32 + idx) = o;
                }
            }
        }
}

// ---------------- attention: 2 queries/thread, f32x2 ----------------
__global__ void __launch_bounds__(128) attn_kernel() {
    __shared__ float4 Ks[128][8];
    __shared__ float4 Vs[128][8];
    const int hd = blockIdx.x, tid = threadIdx.x;
    const int row0 = blockIdx.y * 256 + tid, row1 = row0 + 128;
    const float scale = 0.17677669529663687f;

    unsigned long long q0p[16], q1p[16], o0[16], o1[16];
    {
        const float4* a = (const float4*)(g_qkv + (size_t)row0 * (3 * D) + hd * DH);
        const float4* b = (const float4*)(g_qkv + (size_t)row1 * (3 * D) + hd * DH);
#pragma unroll
        for (int dd = 0; dd < 8; dd++) {
            float4 x = a[dd], y = b[dd];
            PACK2(q0p[2 * dd],     x.x * scale, x.y * scale);
            PACK2(q0p[2 * dd + 1], x.z * scale, x.w * scale);
            PACK2(q1p[2 * dd],     y.x * scale, y.y * scale);
            PACK2(q1p[2 * dd + 1], y.z * scale, y.w * scale);
            o0[2 * dd] = 0; o0[2 * dd + 1] = 0; o1[2 * dd] = 0; o1[2 * dd + 1] = 0;
        }
    }
    float m0 = -1e30f, l0 = 0.f, m1 = -1e30f, l1 = 0.f;
    uint32_t ksu = smem_u32(&Ks[0][0]), vsu = smem_u32(&Vs[0][0]);

    for (int j0 = 0; j0 < NT; j0 += 128) {
#pragma unroll
        for (int i = 0; i < 8; i++) {
            int lin = i * 128 + tid;
            int j = lin >> 3, dd = lin & 7;
            const float* bk = g_qkv + (size_t)(j0 + j) * (3 * D) + D + hd * DH;
            Ks[j][dd] = ((const float4*)bk)[dd];
            Vs[j][dd] = ((const float4*)(bk + D))[dd];
        }
        __syncthreads();
#pragma unroll 2
        for (int j = 0; j < 128; j++) {
            unsigned long long s0 = 0, s1 = 0;
            uint32_t ka = ksu + j * 128;
#pragma unroll
            for (int dd = 0; dd < 8; dd++) {
                unsigned long long u, w;
                LDSV2(u, w, ka + dd * 16);
                FMA2(s0, q0p[2 * dd], u); FMA2(s0, q0p[2 * dd + 1], w);
                FMA2(s1, q1p[2 * dd], u); FMA2(s1, q1p[2 * dd + 1], w);
            }
            float ax, ay, s0f, s1f;
            UNPACK2(ax, ay, s0); s0f = ax + ay;
            UNPACK2(ax, ay, s1); s1f = ax + ay;
            if (s0f > m0) {
                float cc = __expf(m0 - s0f); l0 *= cc;
                unsigned long long cd; PACK2(cd, cc, cc);
#pragma unroll
                for (int i = 0; i < 16; i++) MUL2(o0[i], cd);
                m0 = s0f;
            }
            if (s1f > m1) {
                float cc = __expf(m1 - s1f); l1 *= cc;
                unsigned long long cd; PACK2(cd, cc, cc);
#pragma unroll
                for (int i = 0; i < 16; i++) MUL2(o1[i], cd);
                m1 = s1f;
            }
            float p0 = __expf(s0f - m0); l0 += p0;
            float p1 = __expf(s1f - m1); l1 += p1;
            unsigned long long p0d, p1d;
            PACK2(p0d, p0, p0); PACK2(p1d, p1, p1);
            uint32_t va = vsu + j * 128;
#pragma unroll
            for (int dd = 0; dd < 8; dd++) {
                unsigned long long u, w;
                LDSV2(u, w, va + dd * 16);
                FMA2(o0[2 * dd], p0d, u); FMA2(o0[2 * dd + 1], p0d, w);
                FMA2(o1[2 * dd], p1d, u); FMA2(o1[2 * dd + 1], p1d, w);
            }
        }
        __syncthreads();
    }
    float i0 = 1.f / l0, i1 = 1.f / l1;
    __nv_bfloat16* h0 = g_ao_h + (size_t)row0 * D + hd * DH;
    __nv_bfloat16* l0p = g_ao_l + (size_t)row0 * D + hd * DH;
    __nv_bfloat16* h1 = g_ao_h + (size_t)row1 * D + hd * DH;
    __nv_bfloat16* l1p = g_ao_l + (size_t)row1 * D + hd * DH;
#pragma unroll
    for (int i = 0; i < 16; i++) {
        float a, b; __nv_bfloat16 xh, xl, yh, yl; __nv_bfloat162 p;
        UNPACK2(a, b, o0[i]);
        hilo(a * i0, xh, xl); hilo(b * i0, yh, yl);
        p.x = xh; p.y = yh; *(__nv_bfloat162*)(h0 + 2 * i) = p;
        p.x = xl; p.y = yl; *(__nv_bfloat162*)(l0p + 2 * i) = p;
        UNPACK2(a, b, o1[i]);
        hilo(a * i1, xh, xl); hilo(b * i1, yh, yl);
        p.x = xh; p.y = yh; *(__nv_bfloat162*)(h1 + 2 * i) = p;
        p.x = xl; p.y = yl; *(__nv_bfloat162*)(l1p + 2 * i) = p;
    }
}

// ---------------- conv path ----------------
__global__ void scatter_kernel(const int* __restrict__ coords) {
    int idx = blockIdx.x * blockDim.x + threadIdx.x;
    int n = idx >> 7, d4 = idx & 127;
    int rr = coords[2 * n], cc = coords[2 * n + 1];
    ((float4*)g_grid)[(size_t)(rr * GW + cc) * 128 + d4] =
        ((const float4*)g_x)[(size_t)n * 128 + d4];
}
__global__ void conv_kernel(const float* __restrict__ ck) {
    int idx = blockIdx.x * blockDim.x + threadIdx.x;
    int d = idx & (D - 1), cell = idx >> 9;
    int r = cell >> 6, c = cell & 63;
    float acc = 0.f;
#pragma unroll
    for (int kh = 0; kh < 3; kh++) {
        int rr = r + kh - 1;
        if (rr < 0 || rr >= GH) continue;
#pragma unroll
        for (int kw = 0; kw < 3; kw++) {
            int cc = c + kw - 1;
            if (cc < 0 || cc >= GW) continue;
            acc += ck[d * 9 + kh * 3 + kw] * g_grid[(size_t)(rr * GW + cc) * D + d];
        }
    }
    g_conv[(size_t)cell * D + d] = acc;
}
__global__ void gather_kernel(const int* __restrict__ coords, const float* __restrict__ cb) {
    int idx = blockIdx.x * blockDim.x + threadIdx.x;
    int n = idx >> 9, d = idx & (D - 1);
    int rr = coords[2 * n], cc = coords[2 * n + 1];
    g_x[idx] += g_conv[(size_t)(rr * GW + cc) * D + d] + cb[d];
}

// ---------------- host ----------------
extern "C" void kernel_launch(void* const* d_in, const int* in_sizes, int n_in,
                              void* d_out, int out_size) {
    const float* gf     = (const float*)d_in[0];
    const int*   coords = (const int*)d_in[1];
    int wi = (n_in >= 22) ? 4 : 2;
    const float* ln1_g = (const float*)d_in[wi + 0];
    const float* ln1_b = (const float*)d_in[wi + 1];
    const float* wqkv  = (const float*)d_in[wi + 2];
    const float* bqkv  = (const float*)d_in[wi + 3];
    const float* wo    = (const float*)d_in[wi + 4];
    const float* bo    = (const float*)d_in[wi + 5];
    const float* ln2_g = (const float*)d_in[wi + 6];
    const float* ln2_b = (const float*)d_in[wi + 7];
    const float* w1    = (const float*)d_in[wi + 8];
    const float* b1    = (const float*)d_in[wi + 9];
    const float* w2    = (const float*)d_in[wi + 10];
    const float* b2    = (const float*)d_in[wi + 11];
    const float* ck    = (const float*)d_in[wi + 12];
    const float* cb    = (const float*)d_in[wi + 13];
    const float* lnf_g = (const float*)d_in[wi + 14];
    const float* lnf_b = (const float*)d_in[wi + 15];
    const float* wp    = (const float*)d_in[wi + 16];
    const float* bp    = (const float*)d_in[wi + 17];

    float* out_x    = (float*)d_out;
    float* out_pred = out_x + (size_t)NT * D;

    static float* px = nullptr; static float* pqkv;
    static __nv_bfloat16 *pxnh, *pxnl, *paoh, *paol, *phh, *phl, *pxfh, *pxfl;
    static __nv_bfloat16 *pWqh, *pWql, *pWoh, *pWol, *pW1h, *pW1l, *pW2h, *pW2l, *pWph, *pWpl;
    if (!px) {
        cudaGetSymbolAddress((void**)&px, g_x);
        cudaGetSymbolAddress((void**)&pqkv, g_qkv);
        cudaGetSymbolAddress((void**)&pxnh, g_xn_h); cudaGetSymbolAddress((void**)&pxnl, g_xn_l);
        cudaGetSymbolAddress((void**)&paoh, g_ao_h); cudaGetSymbolAddress((void**)&paol, g_ao_l);
        cudaGetSymbolAddress((void**)&phh, g_hh);    cudaGetSymbolAddress((void**)&phl, g_hl);
        cudaGetSymbolAddress((void**)&pxfh, g_xf_h); cudaGetSymbolAddress((void**)&pxfl, g_xf_l);
        cudaGetSymbolAddress((void**)&pWqh, g_wqkv_h); cudaGetSymbolAddress((void**)&pWql, g_wqkv_l);
        cudaGetSymbolAddress((void**)&pWoh, g_wo_h);   cudaGetSymbolAddress((void**)&pWol, g_wo_l);
        cudaGetSymbolAddress((void**)&pW1h, g_w1_h);   cudaGetSymbolAddress((void**)&pW1l, g_w1_l);
        cudaGetSymbolAddress((void**)&pW2h, g_w2_h);   cudaGetSymbolAddress((void**)&pW2l, g_w2_l);
        cudaGetSymbolAddress((void**)&pWph, g_wp_h);   cudaGetSymbolAddress((void**)&pWpl, g_wp_l);
        cudaFuncSetAttribute(gemm_mma<0>, cudaFuncAttributeMaxDynamicSharedMemorySize, GEMM_DYN);
        cudaFuncSetAttribute(gemm_mma<1>, cudaFuncAttributeMaxDynamicSharedMemorySize, GEMM_DYN);
        cudaFuncSetAttribute(gemm_mma<2>, cudaFuncAttributeMaxDynamicSharedMemorySize, GEMM_DYN);
    }

    // weight hi/lo split
    cvt_kernel<<<(DEPTH * 3 * D * D + 255) / 256, 256>>>(wqkv, pWqh, pWql, DEPTH * 3 * D * D);
    cvt_kernel<<<(DEPTH * D * D + 255) / 256, 256>>>(wo, pWoh, pWol, DEPTH * D * D);
    cvt_kernel<<<(DEPTH * DMLP * D + 255) / 256, 256>>>(w1, pW1h, pW1l, DEPTH * DMLP * D);
    cvt_kernel<<<(DEPTH * D * DMLP + 255) / 256, 256>>>(w2, pW2h, pW2l, DEPTH * D * DMLP);
    cvt_kernel<<<(GENES * D + 255) / 256, 256>>>(wp, pWph, pWpl, GENES * D);

    cudaMemcpyAsync(px, gf, (size_t)NT * D * sizeof(float), cudaMemcpyDeviceToDevice);

    for (int i = 0; i < DEPTH; i++) {
        ln_kernel<0><<<NT, 128>>>(px, nullptr, pxnh, pxnl, ln1_g + i * D, ln1_b + i * D);
        gemm_mma<0><<<dim3(12, 32), 256, GEMM_DYN>>>(
            pxnh, pxnl, pWqh + (size_t)i * 3 * D * D, pWql + (size_t)i * 3 * D * D,
            bqkv + i * 3 * D, pqkv, nullptr, nullptr, 3 * D, D);
        attn_kernel<<<dim3(NHD, NT / 256), 128>>>();
        gemm_mma<2><<<dim3(4, 32), 256, GEMM_DYN>>>(
            paoh, paol, pWoh + (size_t)i * D * D, pWol + (size_t)i * D * D,
            bo + i * D, px, nullptr, nullptr, D, D);
        ln_kernel<0><<<NT, 128>>>(px, nullptr, pxnh, pxnl, ln2_g + i * D, ln2_b + i * D);
        gemm_mma<1><<<dim3(16, 32), 256, GEMM_DYN>>>(
            pxnh, pxnl, pW1h + (size_t)i * DMLP * D, pW1l + (size_t)i * DMLP * D,
            b1 + i * DMLP, nullptr, phh, phl, DMLP, D);
        gemm_mma<2><<<dim3(4, 32), 256, GEMM_DYN>>>(
            phh, phl, pW2h + (size_t)i * D * DMLP, pW2l + (size_t)i * D * DMLP,
            b2 + i * D, px, nullptr, nullptr, D, DMLP);
        scatter_kernel<<<NT * (D / 4) / 256, 256>>>(coords);
        conv_kernel<<<GH * GW * D / 256, 256>>>(ck + (size_t)i * D * 9);
        gather_kernel<<<NT * D / 256, 256>>>(coords, cb + i * D);
    }
    ln_kernel<1><<<NT, 128>>>(px, out_x, pxfh, pxfl, lnf_g, lnf_b);
    gemm_mma<0><<<dim3(2, 32), 256, GEMM_DYN>>>(
        pxfh, pxfl, pWph, pWpl, bp, out_pred, nullptr, nullptr, GENES, D);
}

// round 5
// speedup vs baseline: 3.1791x; 1.9332x over previous
#include <cuda_runtime.h>
#include <cuda_bf16.h>
#include <math.h>
#include <stdint.h>

#define NT    4096
#define D     512
#define NHD   16
#define DH    32
#define DEPTH 3
#define DMLP  2048
#define GENES 250
#define GH    64
#define GW    64

// ---------------- PTX helpers ----------------
__device__ __forceinline__ uint32_t smem_u32(const void* p) {
    uint32_t a;
    asm("{ .reg .u64 t; cvta.to.shared.u64 t, %1; cvt.u32.u64 %0, t; }" : "=r"(a) : "l"(p));
    return a;
}
#define CP_ASYNC16(sa, ga) \
    asm volatile("cp.async.cg.shared.global [%0], [%1], 16;" :: "r"(sa), "l"(ga))
#define CP_COMMIT() asm volatile("cp.async.commit_group;")
#define CP_WAIT(n)  asm volatile("cp.async.wait_group %0;" :: "n"(n))

#define LDSM4(r0, r1, r2, r3, addr) \
    asm volatile("ldmatrix.sync.aligned.m8n8.x4.shared.b16 {%0,%1,%2,%3}, [%4];" \
        : "=r"(r0), "=r"(r1), "=r"(r2), "=r"(r3) : "r"(addr))
#define LDSM4T(r0, r1, r2, r3, addr) \
    asm volatile("ldmatrix.sync.aligned.m8n8.x4.trans.shared.b16 {%0,%1,%2,%3}, [%4];" \
        : "=r"(r0), "=r"(r1), "=r"(r2), "=r"(r3) : "r"(addr))

__device__ __forceinline__ void mma_bf16(float* d, const uint32_t* a, const uint32_t* b) {
    asm volatile("mma.sync.aligned.m16n8k16.row.col.f32.bf16.bf16.f32 "
        "{%0,%1,%2,%3}, {%4,%5,%6,%7}, {%8,%9}, {%0,%1,%2,%3};"
        : "+f"(d[0]), "+f"(d[1]), "+f"(d[2]), "+f"(d[3])
        : "r"(a[0]), "r"(a[1]), "r"(a[2]), "r"(a[3]), "r"(b[0]), "r"(b[1]));
}

// pack two f32 -> bf16x2 (low half = lo arg, high half = hi arg)
#define PACKBF(d, lo, hi) \
    asm("cvt.rn.bf16x2.f32 %0, %1, %2;" : "=r"(d) : "f"(hi), "f"(lo))

__device__ __forceinline__ float ex2f(float x) {
    float y; asm("ex2.approx.f32 %0, %1;" : "=f"(y) : "f"(x)); return y;
}

__device__ __forceinline__ void hilo(float v, __nv_bfloat16& h, __nv_bfloat16& l) {
    h = __float2bfloat16(v);
    l = __float2bfloat16(v - __bfloat162float(h));
}

// ---------------- device scratch ----------------
__device__ float g_x[NT * D];
__device__ float g_grid[GH * GW * D];
__device__ float g_conv[GH * GW * D];
__device__ __nv_bfloat16 g_qkv_h[NT * 3 * D], g_qkv_l[NT * 3 * D];
__device__ __nv_bfloat16 g_xn_h[NT * D],  g_xn_l[NT * D];
__device__ __nv_bfloat16 g_ao_h[NT * D],  g_ao_l[NT * D];
__device__ __nv_bfloat16 g_hh[NT * DMLP], g_hl[NT * DMLP];
__device__ __nv_bfloat16 g_xf_h[NT * D],  g_xf_l[NT * D];
__device__ __nv_bfloat16 g_wqkv_h[DEPTH * 3 * D * D], g_wqkv_l[DEPTH * 3 * D * D];
__device__ __nv_bfloat16 g_wo_h[DEPTH * D * D],       g_wo_l[DEPTH * D * D];
__device__ __nv_bfloat16 g_w1_h[DEPTH * DMLP * D],    g_w1_l[DEPTH * DMLP * D];
__device__ __nv_bfloat16 g_w2_h[DEPTH * D * DMLP],    g_w2_l[DEPTH * D * DMLP];
__device__ __nv_bfloat16 g_wp_h[GENES * D],           g_wp_l[GENES * D];

__global__ void cvt_kernel(const float* __restrict__ s, __nv_bfloat16* __restrict__ h,
                           __nv_bfloat16* __restrict__ l, int n) {
    int i = blockIdx.x * blockDim.x + threadIdx.x;
    if (i < n) { __nv_bfloat16 a, b; hilo(s[i], a, b); h[i] = a; l[i] = b; }
}

// ---------------- LayerNorm -> bf16 hi/lo (optionally fp32 copy) -----------
template <int WF32>
__global__ void ln_kernel(const float* __restrict__ in, float* __restrict__ out32,
                          __nv_bfloat16* __restrict__ oh, __nv_bfloat16* __restrict__ ol,
                          const float* __restrict__ gam, const float* __restrict__ bet) {
    int row = blockIdx.x, t = threadIdx.x;
    float4 v = ((const float4*)(in + (size_t)row * D))[t];
    float s = v.x + v.y + v.z + v.w;
    float ss = v.x * v.x + v.y * v.y + v.z * v.z + v.w * v.w;
#pragma unroll
    for (int off = 16; off; off >>= 1) {
        s  += __shfl_xor_sync(0xffffffffu, s, off);
        ss += __shfl_xor_sync(0xffffffffu, ss, off);
    }
    __shared__ float sb[4], ssb[4];
    int w = t >> 5, lane = t & 31;
    if (lane == 0) { sb[w] = s; ssb[w] = ss; }
    __syncthreads();
    s = sb[0] + sb[1] + sb[2] + sb[3];
    ss = ssb[0] + ssb[1] + ssb[2] + ssb[3];
    float mean = s * (1.0f / D);
    float inv = rsqrtf(ss * (1.0f / D) - mean * mean + 1e-5f);
    float4 g4 = ((const float4*)gam)[t];
    float4 b4 = ((const float4*)bet)[t];
    float o0 = (v.x - mean) * inv * g4.x + b4.x;
    float o1 = (v.y - mean) * inv * g4.y + b4.y;
    float o2 = (v.z - mean) * inv * g4.z + b4.z;
    float o3 = (v.w - mean) * inv * g4.w + b4.w;
    size_t base = (size_t)row * D + t * 4;
    __nv_bfloat16 h0, l0, h1, l1, h2, l2, h3, l3;
    hilo(o0, h0, l0); hilo(o1, h1, l1); hilo(o2, h2, l2); hilo(o3, h3, l3);
    __nv_bfloat162 p;
    p.x = h0; p.y = h1; *(__nv_bfloat162*)(oh + base) = p;
    p.x = h2; p.y = h3; *(__nv_bfloat162*)(oh + base + 2) = p;
    p.x = l0; p.y = l1; *(__nv_bfloat162*)(ol + base) = p;
    p.x = l2; p.y = l3; *(__nv_bfloat162*)(ol + base + 2) = p;
    if (WF32) {
        float4 o; o.x = o0; o.y = o1; o.z = o2; o.w = o3;
        ((float4*)(out32 + (size_t)row * D))[t] = o;
    }
}

// ---------------- bf16 hi/lo 3-term GEMM via mma.sync (HMMA) ----------------
#define TPITCH 80
#define TILE_B (128 * TPITCH)
#define STAGE_B (4 * TILE_B)
#define GEMM_DYN (2 * STAGE_B)

__device__ __forceinline__ void stage_load(
    uint32_t sbase, const __nv_bfloat16* Ah, const __nv_bfloat16* Al,
    const __nv_bfloat16* Wh, const __nv_bfloat16* Wl,
    int mrow, int ncol, int OUT, int K, int kt, int tid) {
#pragma unroll
    for (int i = 0; i < 2; i++) {
        int chunk = tid + i * 256;
        int r = chunk >> 2, c16 = chunk & 3;
        uint32_t so = (uint32_t)(r * TPITCH + c16 * 16);
        size_t aoff = (size_t)(mrow + r) * K + kt + c16 * 8;
        int wr = ncol + r; if (wr >= OUT) wr = OUT - 1;
        size_t woff = (size_t)wr * K + kt + c16 * 8;
        CP_ASYNC16(sbase + so,              (const char*)(Ah + aoff));
        CP_ASYNC16(sbase + TILE_B + so,     (const char*)(Al + aoff));
        CP_ASYNC16(sbase + 2 * TILE_B + so, (const char*)(Wh + woff));
        CP_ASYNC16(sbase + 3 * TILE_B + so, (const char*)(Wl + woff));
    }
}

// MODE 0: out32=v+bias ; 1: outh/l=hilo(gelu(v+bias)) ; 2: out32+=v+bias ; 3: outh/l=hilo(v+bias)
template <int MODE>
__global__ void __launch_bounds__(256) gemm_mma(
    const __nv_bfloat16* __restrict__ Ah, const __nv_bfloat16* __restrict__ Al,
    const __nv_bfloat16* __restrict__ Wh, const __nv_bfloat16* __restrict__ Wl,
    const float* __restrict__ bias, float* __restrict__ out32,
    __nv_bfloat16* __restrict__ outh, __nv_bfloat16* __restrict__ outl,
    int OUT, int K) {
    extern __shared__ char dyn_raw[];
    const int tid = threadIdx.x, wid = tid >> 5, lane = tid & 31;
    const int mrow = blockIdx.y * 128, ncol = blockIdx.x * 128;
    const int warp_m = wid & 1, warp_n = wid >> 1;
    const int m_off = warp_m * 64, n_off = warp_n * 32;
    const int NIT = K >> 5;
    uint32_t smem0 = smem_u32(dyn_raw);

    float acc[4][4][4];
#pragma unroll
    for (int a = 0; a < 4; a++)
#pragma unroll
        for (int b = 0; b < 4; b++)
#pragma unroll
            for (int c = 0; c < 4; c++) acc[a][b][c] = 0.f;

    const uint32_t a_lm = (uint32_t)((m_off + (lane & 15)) * TPITCH + (lane & 16));
    const int bl = lane & 7, bg = (lane >> 3) & 3;
    const uint32_t b_lm = (uint32_t)((n_off + ((bg >> 1) << 3) + bl) * TPITCH + ((bg & 1) << 4));

    stage_load(smem0, Ah, Al, Wh, Wl, mrow, ncol, OUT, K, 0, tid);
    CP_COMMIT();

    for (int it = 0; it < NIT; it++) {
        if (it + 1 < NIT) {
            stage_load(smem0 + ((it + 1) & 1) * STAGE_B, Ah, Al, Wh, Wl,
                       mrow, ncol, OUT, K, (it + 1) * 32, tid);
            CP_COMMIT();
            CP_WAIT(1);
        } else {
            CP_WAIT(0);
        }
        __syncthreads();
        uint32_t sb = smem0 + (it & 1) * STAGE_B;
#pragma unroll
        for (int ks = 0; ks < 2; ks++) {
            uint32_t kb = (uint32_t)(ks * 32);
            uint32_t ah[4][4], al[4][4], bh[4][2], bl2[4][2];
#pragma unroll
            for (int mt = 0; mt < 4; mt++) {
                uint32_t ad = sb + a_lm + mt * (16 * TPITCH) + kb;
                LDSM4(ah[mt][0], ah[mt][1], ah[mt][2], ah[mt][3], ad);
                LDSM4(al[mt][0], al[mt][1], al[mt][2], al[mt][3], ad + TILE_B);
            }
#pragma unroll
            for (int np = 0; np < 2; np++) {
                uint32_t bd = sb + 2 * TILE_B + b_lm + np * (16 * TPITCH) + kb;
                LDSM4(bh[2 * np][0], bh[2 * np][1], bh[2 * np + 1][0], bh[2 * np + 1][1], bd);
                LDSM4(bl2[2 * np][0], bl2[2 * np][1], bl2[2 * np + 1][0], bl2[2 * np + 1][1], bd + TILE_B);
            }
#pragma unroll
            for (int mt = 0; mt < 4; mt++)
#pragma unroll
                for (int nt = 0; nt < 4; nt++) {
                    mma_bf16(acc[mt][nt], ah[mt], bh[nt]);
                    mma_bf16(acc[mt][nt], ah[mt], bl2[nt]);
                    mma_bf16(acc[mt][nt], al[mt], bh[nt]);
                }
        }
        __syncthreads();
    }

    const int r0 = lane >> 2, cp = (lane & 3) * 2;
#pragma unroll
    for (int mt = 0; mt < 4; mt++)
#pragma unroll
        for (int nt = 0; nt < 4; nt++) {
            int col = ncol + n_off + nt * 8 + cp;
            if (col >= OUT) continue;
            float bx = bias[col], by = bias[col + 1];
#pragma unroll
            for (int half = 0; half < 2; half++) {
                int row = mrow + m_off + mt * 16 + r0 + half * 8;
                float vx = acc[mt][nt][2 * half] + bx;
                float vy = acc[mt][nt][2 * half + 1] + by;
                size_t idx = (size_t)row * OUT + col;
                if (MODE == 0) {
                    *(float2*)(out32 + idx) = make_float2(vx, vy);
                } else if (MODE == 1 || MODE == 3) {
                    if (MODE == 1) {
                        vx = 0.5f * vx * (1.0f + erff(vx * 0.70710678118654752f));
                        vy = 0.5f * vy * (1.0f + erff(vy * 0.70710678118654752f));
                    }
                    __nv_bfloat16 hx, lx, hy, ly;
                    hilo(vx, hx, lx); hilo(vy, hy, ly);
                    __nv_bfloat162 p;
                    p.x = hx; p.y = hy; *(__nv_bfloat162*)(outh + idx) = p;
                    p.x = lx; p.y = ly; *(__nv_bfloat162*)(outl + idx) = p;
                } else {
                    float2 o = *(float2*)(out32 + idx);
                    o.x += vx; o.y += vy;
                    *(float2*)(out32 + idx) = o;
                }
            }
        }
}

// ---------------- flash attention on HMMA, bf16 hi/lo 3-term -----------------
// CTA = (head, 64-query block). 4 warps x 16 rows. K/V tiles of 64 keys,
// cp.async double-buffered. S frag -> P (bf16 hi/lo) -> PV with ldmatrix.trans V.
#define AP 80
#define KVT (64 * AP)
#define ASTG (4 * KVT)

__global__ void __launch_bounds__(128) attn_tc() {
    __shared__ __align__(16) char smem[2 * ASTG];
    const int tid = threadIdx.x, wid = tid >> 5, lane = tid & 31;
    const int h = blockIdx.x, qb = blockIdx.y * 64;
    const uint32_t s0 = smem_u32(smem);

    // ---- stage Q (64x32 hi/lo) and load fragments
#pragma unroll
    for (int i = 0; i < 4; i++) {
        int idx = tid + i * 128;
        int tile = idx >> 8, rem = idx & 255, r = rem >> 2, c = rem & 3;
        const __nv_bfloat16* src = (tile ? g_qkv_l : g_qkv_h) + (size_t)(qb + r) * 1536 + h * 32 + c * 8;
        CP_ASYNC16(s0 + tile * KVT + r * AP + c * 16, src);
    }
    CP_COMMIT(); CP_WAIT(0); __syncthreads();
    uint32_t qh[2][4], ql[2][4];
    {
        uint32_t alm = s0 + (wid * 16 + (lane & 15)) * AP + (lane & 16);
        LDSM4(qh[0][0], qh[0][1], qh[0][2], qh[0][3], alm);
        LDSM4(qh[1][0], qh[1][1], qh[1][2], qh[1][3], alm + 32);
        LDSM4(ql[0][0], ql[0][1], ql[0][2], ql[0][3], alm + KVT);
        LDSM4(ql[1][0], ql[1][1], ql[1][2], ql[1][3], alm + KVT + 32);
    }
    __syncthreads();

    const int bl = lane & 7, bg = (lane >> 3) & 3;
    const uint32_t koff = (uint32_t)((((bg >> 1) * 8) + bl) * AP + ((bg & 1) * 16));
    const uint32_t voff = (uint32_t)(((((lane >> 3) & 1) * 8) + (lane & 7)) * AP + (((lane >> 4) & 1) * 16));

    float O[4][4];
#pragma unroll
    for (int a = 0; a < 4; a++)
#pragma unroll
        for (int b = 0; b < 4; b++) O[a][b] = 0.f;
    float m0 = -1e30f, m1 = -1e30f, lsum0 = 0.f, lsum1 = 0.f;
    const float sc2 = 0.25501649f;   // (1/sqrt(32)) * log2(e)

    // prologue: tile 0
    {
#pragma unroll
        for (int i = 0; i < 8; i++) {
            int idx = tid + i * 128;
            int tile = idx >> 8, rem = idx & 255, r = rem >> 2, c = rem & 3;
            const __nv_bfloat16* base = (tile & 1) ? g_qkv_l : g_qkv_h;
            int col = ((tile >> 1) ? 1024 : 512) + h * 32;
            CP_ASYNC16(s0 + tile * KVT + r * AP + c * 16,
                       base + (size_t)r * 1536 + col + c * 8);
        }
        CP_COMMIT();
    }

    for (int t = 0; t < NT / 64; t++) {
        if (t + 1 < NT / 64) {
            int kb = (t + 1) * 64;
            uint32_t st = s0 + ((t + 1) & 1) * ASTG;
#pragma unroll
            for (int i = 0; i < 8; i++) {
                int idx = tid + i * 128;
                int tile = idx >> 8, rem = idx & 255, r = rem >> 2, c = rem & 3;
                const __nv_bfloat16* base = (tile & 1) ? g_qkv_l : g_qkv_h;
                int col = ((tile >> 1) ? 1024 : 512) + h * 32;
                CP_ASYNC16(st + tile * KVT + r * AP + c * 16,
                           base + (size_t)(kb + r) * 1536 + col + c * 8);
            }
            CP_COMMIT(); CP_WAIT(1);
        } else {
            CP_WAIT(0);
        }
        __syncthreads();
        uint32_t sb = s0 + (t & 1) * ASTG;

        // ---- S = Q K^T (3-term)
        float S[8][4];
#pragma unroll
        for (int a = 0; a < 8; a++)
#pragma unroll
            for (int b = 0; b < 4; b++) S[a][b] = 0.f;
#pragma unroll
        for (int ks = 0; ks < 2; ks++) {
            uint32_t kh[8][2], kl[8][2];
#pragma unroll
            for (int np = 0; np < 4; np++) {
                uint32_t ad = sb + np * (16 * AP) + koff + ks * 32;
                LDSM4(kh[2 * np][0], kh[2 * np][1], kh[2 * np + 1][0], kh[2 * np + 1][1], ad);
                LDSM4(kl[2 * np][0], kl[2 * np][1], kl[2 * np + 1][0], kl[2 * np + 1][1], ad + KVT);
            }
#pragma unroll
            for (int nt = 0; nt < 8; nt++) {
                mma_bf16(S[nt], qh[ks], kh[nt]);
                mma_bf16(S[nt], qh[ks], kl[nt]);
                mma_bf16(S[nt], ql[ks], kh[nt]);
            }
        }

        // ---- online softmax (rows: r = lane>>2 and r+8; cols spread over quad)
        float t0 = -1e30f, t1 = -1e30f;
#pragma unroll
        for (int nt = 0; nt < 8; nt++) {
            t0 = fmaxf(t0, fmaxf(S[nt][0], S[nt][1]));
            t1 = fmaxf(t1, fmaxf(S[nt][2], S[nt][3]));
        }
        t0 *= sc2; t1 *= sc2;
        t0 = fmaxf(t0, __shfl_xor_sync(0xffffffffu, t0, 1));
        t0 = fmaxf(t0, __shfl_xor_sync(0xffffffffu, t0, 2));
        t1 = fmaxf(t1, __shfl_xor_sync(0xffffffffu, t1, 1));
        t1 = fmaxf(t1, __shfl_xor_sync(0xffffffffu, t1, 2));
        float mn0 = fmaxf(m0, t0), mn1 = fmaxf(m1, t1);
        float c0 = ex2f(m0 - mn0), c1 = ex2f(m1 - mn1);
        m0 = mn0; m1 = mn1;
        lsum0 *= c0; lsum1 *= c1;
#pragma unroll
        for (int nt = 0; nt < 4; nt++) {
            O[nt][0] *= c0; O[nt][1] *= c0; O[nt][2] *= c1; O[nt][3] *= c1;
        }
        uint32_t ph01[8], ph23[8], pl01[8], pl23[8];
#pragma unroll
        for (int nt = 0; nt < 8; nt++) {
            float p0 = ex2f(fmaf(S[nt][0], sc2, -m0));
            float p1 = ex2f(fmaf(S[nt][1], sc2, -m0));
            float p2 = ex2f(fmaf(S[nt][2], sc2, -m1));
            float p3 = ex2f(fmaf(S[nt][3], sc2, -m1));
            lsum0 += p0 + p1; lsum1 += p2 + p3;
            uint32_t hp, lp;
            PACKBF(hp, p0, p1); ph01[nt] = hp;
            float h0f = __uint_as_float(hp << 16);
            float h1f = __uint_as_float(hp & 0xffff0000u);
            PACKBF(lp, p0 - h0f, p1 - h1f); pl01[nt] = lp;
            PACKBF(hp, p2, p3); ph23[nt] = hp;
            h0f = __uint_as_float(hp << 16);
            h1f = __uint_as_float(hp & 0xffff0000u);
            PACKBF(lp, p2 - h0f, p3 - h1f); pl23[nt] = lp;
        }

        // ---- O += P V (3-term), V via ldmatrix.trans
#pragma unroll
        for (int s = 0; s < 4; s++) {
            uint32_t aH[4] = { ph01[2 * s], ph23[2 * s], ph01[2 * s + 1], ph23[2 * s + 1] };
            uint32_t aL[4] = { pl01[2 * s], pl23[2 * s], pl01[2 * s + 1], pl23[2 * s + 1] };
            uint32_t vh[4][2], vl[4][2];
#pragma unroll
            for (int d2 = 0; d2 < 2; d2++) {
                uint32_t ad = sb + 2 * KVT + s * (16 * AP) + voff + d2 * 32;
                LDSM4T(vh[2 * d2][0], vh[2 * d2][1], vh[2 * d2 + 1][0], vh[2 * d2 + 1][1], ad);
                LDSM4T(vl[2 * d2][0], vl[2 * d2][1], vl[2 * d2 + 1][0], vl[2 * d2 + 1][1], ad + KVT);
            }
#pragma unroll
            for (int nt = 0; nt < 4; nt++) {
                mma_bf16(O[nt], aH, vh[nt]);
                mma_bf16(O[nt], aH, vl[nt]);
                mma_bf16(O[nt], aL, vh[nt]);
            }
        }
        __syncthreads();
    }

    // ---- epilogue
    lsum0 += __shfl_xor_sync(0xffffffffu, lsum0, 1);
    lsum0 += __shfl_xor_sync(0xffffffffu, lsum0, 2);
    lsum1 += __shfl_xor_sync(0xffffffffu, lsum1, 1);
    lsum1 += __shfl_xor_sync(0xffffffffu, lsum1, 2);
    float i0 = 1.f / lsum0, i1 = 1.f / lsum1;
    int r0 = qb + wid * 16 + (lane >> 2), r1 = r0 + 8;
    int colb = h * 32 + (lane & 3) * 2;
#pragma unroll
    for (int nt = 0; nt < 4; nt++) {
        int col = colb + nt * 8;
        float v0 = O[nt][0] * i0, v1 = O[nt][1] * i0;
        float v2 = O[nt][2] * i1, v3 = O[nt][3] * i1;
        uint32_t hp, lp;
        PACKBF(hp, v0, v1);
        float h0f = __uint_as_float(hp << 16), h1f = __uint_as_float(hp & 0xffff0000u);
        PACKBF(lp, v0 - h0f, v1 - h1f);
        *(uint32_t*)(g_ao_h + (size_t)r0 * D + col) = hp;
        *(uint32_t*)(g_ao_l + (size_t)r0 * D + col) = lp;
        PACKBF(hp, v2, v3);
        h0f = __uint_as_float(hp << 16); h1f = __uint_as_float(hp & 0xffff0000u);
        PACKBF(lp, v2 - h0f, v3 - h1f);
        *(uint32_t*)(g_ao_h + (size_t)r1 * D + col) = hp;
        *(uint32_t*)(g_ao_l + (size_t)r1 * D + col) = lp;
    }
}

// ---------------- conv path ----------------
__global__ void scatter_kernel(const int* __restrict__ coords) {
    int idx = blockIdx.x * blockDim.x + threadIdx.x;
    int n = idx >> 7, d4 = idx & 127;
    int rr = coords[2 * n], cc = coords[2 * n + 1];
    ((float4*)g_grid)[(size_t)(rr * GW + cc) * 128 + d4] =
        ((const float4*)g_x)[(size_t)n * 128 + d4];
}
__global__ void conv_kernel(const float* __restrict__ ck) {
    int idx = blockIdx.x * blockDim.x + threadIdx.x;
    int d = idx & (D - 1), cell = idx >> 9;
    int r = cell >> 6, c = cell & 63;
    float acc = 0.f;
#pragma unroll
    for (int kh = 0; kh < 3; kh++) {
        int rr = r + kh - 1;
        if (rr < 0 || rr >= GH) continue;
#pragma unroll
        for (int kw = 0; kw < 3; kw++) {
            int cc = c + kw - 1;
            if (cc < 0 || cc >= GW) continue;
            acc += ck[d * 9 + kh * 3 + kw] * g_grid[(size_t)(rr * GW + cc) * D + d];
        }
    }
    g_conv[(size_t)cell * D + d] = acc;
}
__global__ void gather_kernel(const int* __restrict__ coords, const float* __restrict__ cb) {
    int idx = blockIdx.x * blockDim.x + threadIdx.x;
    int n = idx >> 9, d = idx & (D - 1);
    int rr = coords[2 * n], cc = coords[2 * n + 1];
    g_x[idx] += g_conv[(size_t)(rr * GW + cc) * D + d] + cb[d];
}

// ---------------- host ----------------
extern "C" void kernel_launch(void* const* d_in, const int* in_sizes, int n_in,
                              void* d_out, int out_size) {
    const float* gf     = (const float*)d_in[0];
    const int*   coords = (const int*)d_in[1];
    int wi = (n_in >= 22) ? 4 : 2;
    const float* ln1_g = (const float*)d_in[wi + 0];
    const float* ln1_b = (const float*)d_in[wi + 1];
    const float* wqkv  = (const float*)d_in[wi + 2];
    const float* bqkv  = (const float*)d_in[wi + 3];
    const float* wo    = (const float*)d_in[wi + 4];
    const float* bo    = (const float*)d_in[wi + 5];
    const float* ln2_g = (const float*)d_in[wi + 6];
    const float* ln2_b = (const float*)d_in[wi + 7];
    const float* w1    = (const float*)d_in[wi + 8];
    const float* b1    = (const float*)d_in[wi + 9];
    const float* w2    = (const float*)d_in[wi + 10];
    const float* b2    = (const float*)d_in[wi + 11];
    const float* ck    = (const float*)d_in[wi + 12];
    const float* cb    = (const float*)d_in[wi + 13];
    const float* lnf_g = (const float*)d_in[wi + 14];
    const float* lnf_b = (const float*)d_in[wi + 15];
    const float* wp    = (const float*)d_in[wi + 16];
    const float* bp    = (const float*)d_in[wi + 17];

    float* out_x    = (float*)d_out;
    float* out_pred = out_x + (size_t)NT * D;

    static float* px = nullptr;
    static __nv_bfloat16 *pqh, *pql, *pxnh, *pxnl, *paoh, *paol, *phh, *phl, *pxfh, *pxfl;
    static __nv_bfloat16 *pWqh, *pWql, *pWoh, *pWol, *pW1h, *pW1l, *pW2h, *pW2l, *pWph, *pWpl;
    if (!px) {
        cudaGetSymbolAddress((void**)&px, g_x);
        cudaGetSymbolAddress((void**)&pqh, g_qkv_h);  cudaGetSymbolAddress((void**)&pql, g_qkv_l);
        cudaGetSymbolAddress((void**)&pxnh, g_xn_h);  cudaGetSymbolAddress((void**)&pxnl, g_xn_l);
        cudaGetSymbolAddress((void**)&paoh, g_ao_h);  cudaGetSymbolAddress((void**)&paol, g_ao_l);
        cudaGetSymbolAddress((void**)&phh, g_hh);     cudaGetSymbolAddress((void**)&phl, g_hl);
        cudaGetSymbolAddress((void**)&pxfh, g_xf_h);  cudaGetSymbolAddress((void**)&pxfl, g_xf_l);
        cudaGetSymbolAddress((void**)&pWqh, g_wqkv_h); cudaGetSymbolAddress((void**)&pWql, g_wqkv_l);
        cudaGetSymbolAddress((void**)&pWoh, g_wo_h);   cudaGetSymbolAddress((void**)&pWol, g_wo_l);
        cudaGetSymbolAddress((void**)&pW1h, g_w1_h);   cudaGetSymbolAddress((void**)&pW1l, g_w1_l);
        cudaGetSymbolAddress((void**)&pW2h, g_w2_h);   cudaGetSymbolAddress((void**)&pW2l, g_w2_l);
        cudaGetSymbolAddress((void**)&pWph, g_wp_h);   cudaGetSymbolAddress((void**)&pWpl, g_wp_l);
        cudaFuncSetAttribute(gemm_mma<0>, cudaFuncAttributeMaxDynamicSharedMemorySize, GEMM_DYN);
        cudaFuncSetAttribute(gemm_mma<1>, cudaFuncAttributeMaxDynamicSharedMemorySize, GEMM_DYN);
        cudaFuncSetAttribute(gemm_mma<2>, cudaFuncAttributeMaxDynamicSharedMemorySize, GEMM_DYN);
        cudaFuncSetAttribute(gemm_mma<3>, cudaFuncAttributeMaxDynamicSharedMemorySize, GEMM_DYN);
    }

    cvt_kernel<<<(DEPTH * 3 * D * D + 255) / 256, 256>>>(wqkv, pWqh, pWql, DEPTH * 3 * D * D);
    cvt_kernel<<<(DEPTH * D * D + 255) / 256, 256>>>(wo, pWoh, pWol, DEPTH * D * D);
    cvt_kernel<<<(DEPTH * DMLP * D + 255) / 256, 256>>>(w1, pW1h, pW1l, DEPTH * DMLP * D);
    cvt_kernel<<<(DEPTH * D * DMLP + 255) / 256, 256>>>(w2, pW2h, pW2l, DEPTH * D * DMLP);
    cvt_kernel<<<(GENES * D + 255) / 256, 256>>>(wp, pWph, pWpl, GENES * D);

    cudaMemcpyAsync(px, gf, (size_t)NT * D * sizeof(float), cudaMemcpyDeviceToDevice);

    for (int i = 0; i < DEPTH; i++) {
        ln_kernel<0><<<NT, 128>>>(px, nullptr, pxnh, pxnl, ln1_g + i * D, ln1_b + i * D);
        gemm_mma<3><<<dim3(12, 32), 256, GEMM_DYN>>>(
            pxnh, pxnl, pWqh + (size_t)i * 3 * D * D, pWql + (size_t)i * 3 * D * D,
            bqkv + i * 3 * D, nullptr, pqh, pql, 3 * D, D);
        attn_tc<<<dim3(NHD, NT / 64), 128>>>();
        gemm_mma<2><<<dim3(4, 32), 256, GEMM_DYN>>>(
            paoh, paol, pWoh + (size_t)i * D * D, pWol + (size_t)i * D * D,
            bo + i * D, px, nullptr, nullptr, D, D);
        ln_kernel<0><<<NT, 128>>>(px, nullptr, pxnh, pxnl, ln2_g + i * D, ln2_b + i * D);
        gemm_mma<1><<<dim3(16, 32), 256, GEMM_DYN>>>(
            pxnh, pxnl, pW1h + (size_t)i * DMLP * D, pW1l + (size_t)i * DMLP * D,
            b1 + i * DMLP, nullptr, phh, phl, DMLP, D);
        gemm_mma<2><<<dim3(4, 32), 256, GEMM_DYN>>>(
            phh, phl, pW2h + (size_t)i * D * DMLP, pW2l + (size_t)i * D * DMLP,
            b2 + i * D, px, nullptr, nullptr, D, DMLP);
        scatter_kernel<<<NT * (D / 4) / 256, 256>>>(coords);
        conv_kernel<<<GH * GW * D / 256, 256>>>(ck + (size_t)i * D * 9);
        gather_kernel<<<NT * D / 256, 256>>>(coords, cb + i * D);
    }
    ln_kernel<1><<<NT, 128>>>(px, out_x, pxfh, pxfl, lnf_g, lnf_b);
    gemm_mma<0><<<dim3(2, 32), 256, GEMM_DYN>>>(
        pxfh, pxfl, pWph, pWpl, bp, out_pred, nullptr, nullptr, GENES, D);
}